// round 1
// baseline (speedup 1.0000x reference)
#include <cuda_runtime.h>
#include <math.h>
#include <float.h>

#define BB 16
#define SS 64
#define MM 2048
#define DD 256
#define TK 8

// Persistent per-launch state (re-initialized every call; no runtime allocs).
__device__ float g_mem[BB*MM*DD];      // per-batch memory bank
__device__ float g_K[BB*MM*DD];        // cached keys  = mem @ Wk^T + bk
__device__ float g_V[BB*MM*DD];        // cached values= mem @ Wv^T + bv
__device__ float g_WqT[DD*DD];
__device__ float g_WkT[DD*DD];
__device__ float g_WvT[DD*DD];
__device__ float g_WuT[2*DD*DD];
__device__ float g_scores[BB*MM];
__device__ float g_partial[BB*16*DD];
__device__ float g_q[BB*DD];
__device__ float g_memout[BB*DD];
__device__ float g_upd[BB*TK*DD];
__device__ int   g_idx[BB*TK];

// ---------------- init kernels ----------------

__global__ void k_transpose(const float* __restrict__ Wq, const float* __restrict__ Wk,
                            const float* __restrict__ Wv, const float* __restrict__ Wu){
  for (int i = blockIdx.x*blockDim.x + threadIdx.x; i < 2*DD*DD; i += gridDim.x*blockDim.x){
    if (i < DD*DD){
      int d = i / DD, j = i % DD;
      g_WqT[j*DD+d] = Wq[i];
      g_WkT[j*DD+d] = Wk[i];
      g_WvT[j*DD+d] = Wv[i];
    }
    int d = i / (2*DD), j = i % (2*DD);   // Wu is [DD][2*DD]
    g_WuT[j*DD+d] = Wu[i];
  }
}

// 16 memory rows per block; broadcast K/V/mem into all 16 batches.
__global__ void k_init_kv(const float* __restrict__ memory,
                          const float* __restrict__ bk, const float* __restrict__ bv){
  __shared__ float sm[16*DD];
  int r0 = blockIdx.x * 16;
  int tid = threadIdx.x;
  for (int i = tid; i < 16*DD; i += 256) sm[i] = memory[(size_t)r0*DD + i];
  __syncthreads();
  float accK[16], accV[16];
  #pragma unroll
  for (int r=0;r<16;r++){ accK[r]=0.f; accV[r]=0.f; }
  for (int j=0;j<DD;j++){
    float wk = g_WkT[j*DD+tid], wv = g_WvT[j*DD+tid];
    #pragma unroll
    for (int r=0;r<16;r++){
      float m = sm[r*DD+j];
      accK[r] = fmaf(wk, m, accK[r]);
      accV[r] = fmaf(wv, m, accV[r]);
    }
  }
  float bkd = bk[tid], bvd = bv[tid];
  for (int r=0;r<16;r++){
    int m = r0 + r;
    float kk = accK[r]+bkd, vv = accV[r]+bvd, mv = sm[r*DD+tid];
    for (int b=0;b<BB;b++){
      size_t off = ((size_t)(b*MM+m))*DD + tid;
      g_K[off]=kk; g_V[off]=vv; g_mem[off]=mv;
    }
  }
}

__global__ void k_init_q(const float* __restrict__ x, const float* __restrict__ bq){
  __shared__ float xs[DD];
  int b = blockIdx.x, tid = threadIdx.x;
  xs[tid] = x[((size_t)b*SS+0)*DD + tid];
  __syncthreads();
  float acc = 0.f;
  #pragma unroll 4
  for (int j=0;j<DD;j++) acc = fmaf(g_WqT[j*DD+tid], xs[j], acc);
  g_q[b*DD+tid] = acc + bq[tid];
}

// ---------------- per-step kernels ----------------

// scores[b][m] = (q[b] . K[b][m]) * scale.  grid (32, B), 256 thr; warp per row.
__global__ void k_scores(){
  __shared__ float qs[DD];
  int b = blockIdx.y, c = blockIdx.x, tid = threadIdx.x;
  qs[tid] = g_q[b*DD+tid];
  __syncthreads();
  int warp = tid>>5, lane = tid&31;
  #pragma unroll
  for (int r=0;r<8;r++){
    int m = c*64 + warp*8 + r;
    const float* kr = g_K + ((size_t)(b*MM+m))*DD;
    float s = 0.f;
    #pragma unroll
    for (int e=0;e<8;e++) s = fmaf(kr[lane+32*e], qs[lane+32*e], s);
    #pragma unroll
    for (int off=16; off; off>>=1) s += __shfl_xor_sync(0xffffffffu, s, off);
    if (lane==0) g_scores[b*MM+m] = s * 0.0625f;   // 1/sqrt(256)
  }
}

// partial[b][c][d] = sum_{m in chunk c} softmax(scores)[m] * V[b][m][d]. grid (16, B).
__global__ void k_memout(){
  __shared__ float red[256];
  __shared__ float attn[128];
  int b = blockIdx.y, c = blockIdx.x, tid = threadIdx.x;
  const float* sc = g_scores + b*MM;
  float lm = -FLT_MAX;
  for (int m=tid;m<MM;m+=256) lm = fmaxf(lm, sc[m]);
  red[tid]=lm; __syncthreads();
  for (int off=128;off;off>>=1){ if(tid<off) red[tid]=fmaxf(red[tid],red[tid+off]); __syncthreads(); }
  float mx = red[0]; __syncthreads();
  float ls = 0.f;
  for (int m=tid;m<MM;m+=256) ls += expf(sc[m]-mx);
  red[tid]=ls; __syncthreads();
  for (int off=128;off;off>>=1){ if(tid<off) red[tid]+=red[tid+off]; __syncthreads(); }
  float inv = 1.0f/red[0];
  if (tid<128) attn[tid] = expf(sc[c*128+tid]-mx)*inv;
  __syncthreads();
  const float* vb = g_V + ((size_t)(b*MM + c*128))*DD + tid;
  float acc = 0.f;
  #pragma unroll 8
  for (int l=0;l<128;l++) acc = fmaf(attn[l], vb[(size_t)l*DD], acc);
  g_partial[(b*16+c)*DD+tid] = acc;
}

// Reduce partials -> mem_out, write output row, top-8 argmax (destructive on scores). grid B.
__global__ void k_f1(float* __restrict__ out, int t){
  __shared__ float sv[256];
  __shared__ int   si[256];
  int b = blockIdx.x, tid = threadIdx.x;
  float mo = 0.f;
  #pragma unroll
  for (int c=0;c<16;c++) mo += g_partial[(b*16+c)*DD+tid];
  g_memout[b*DD+tid] = mo;
  out[((size_t)b*SS+t)*DD+tid] = mo;
  float* sc = g_scores + b*MM;
  for (int k2=0;k2<TK;k2++){
    float v = -FLT_MAX; int bi = MM;
    for (int m=tid;m<MM;m+=256){
      float s = sc[m];
      if (s > v){ v = s; bi = m; }       // strict > keeps lowest index on ties
    }
    sv[tid]=v; si[tid]=bi; __syncthreads();
    for (int off=128;off;off>>=1){
      if (tid<off){
        if (sv[tid+off]>sv[tid] || (sv[tid+off]==sv[tid] && si[tid+off]<si[tid])){
          sv[tid]=sv[tid+off]; si[tid]=si[tid+off];
        }
      }
      __syncthreads();
    }
    if (tid==0){ g_idx[b*TK+k2] = si[0]; sc[si[0]] = -FLT_MAX; }
    __syncthreads();
  }
}

// gate + row updates (write mem + g_upd). grid (4, B); block covers 64 d's, 4 j-groups.
__global__ void k_f2(const float* __restrict__ x, const float* __restrict__ bu, int t){
  __shared__ float cat[2*DD];
  __shared__ float red[256];
  __shared__ float gsm[64];
  __shared__ int idxs[TK];
  int b = blockIdx.y, dc = blockIdx.x, tid = threadIdx.x;
  int dl = tid & 63, jg = tid >> 6;
  int d = dc*64 + dl;
  cat[tid]     = x[((size_t)b*SS+t)*DD + tid];
  cat[DD+tid]  = g_memout[b*DD+tid];
  if (tid < TK) idxs[tid] = g_idx[b*TK+tid];
  __syncthreads();
  float acc = 0.f;
  #pragma unroll 4
  for (int j=jg; j<2*DD; j+=4) acc = fmaf(g_WuT[j*DD+d], cat[j], acc);
  red[tid]=acc; __syncthreads();
  if (jg==0){
    float g = red[dl]+red[64+dl]+red[128+dl]+red[192+dl] + bu[d];
    gsm[dl] = 1.0f/(1.0f+expf(-g));
  }
  __syncthreads();
  float gate = gsm[dl];
  float xd = cat[d];
  for (int ii=jg; ii<TK; ii+=4){
    int row = idxs[ii];
    size_t off = ((size_t)(b*MM+row))*DD + d;
    float m = g_mem[off];
    float u = m + gate*(xd - m);          // (1-g)*m + g*x
    g_mem[off] = u;
    g_upd[(b*TK+ii)*DD + d] = u;
  }
}

// Re-encode the 8 updated rows through Wk/Wv, and q for step t+1. grid (8, B).
__global__ void k_f3(const float* __restrict__ x, const float* __restrict__ bq,
                     const float* __restrict__ bk, const float* __restrict__ bv, int t){
  __shared__ __align__(16) float updT[DD*TK];  // [j][i]
  __shared__ float xn[DD];
  __shared__ int idxs[TK];
  __shared__ float pk[8][TK][32];
  __shared__ float pv[8][TK][32];
  __shared__ float pq[8][32];
  int b = blockIdx.y, dc = blockIdx.x, tid = threadIdx.x;
  int dl = tid & 31, jg = tid >> 5;
  int d = dc*32 + dl;
  for (int l = tid; l < TK*DD; l += 256){
    int i = l >> 8, j = l & 255;
    updT[j*TK+i] = g_upd[b*TK*DD + l];
  }
  bool hasq = (t+1 < SS);
  xn[tid] = hasq ? x[((size_t)b*SS + (t+1))*DD + tid] : 0.f;
  if (tid < TK) idxs[tid] = g_idx[b*TK+tid];
  __syncthreads();
  float accK[TK], accV[TK], accQ = 0.f;
  #pragma unroll
  for (int i=0;i<TK;i++){ accK[i]=0.f; accV[i]=0.f; }
  #pragma unroll 4
  for (int j=jg; j<DD; j+=8){
    float wk = g_WkT[j*DD+d];
    float wv = g_WvT[j*DD+d];
    float wq = g_WqT[j*DD+d];
    accQ = fmaf(wq, xn[j], accQ);
    float uu[TK];
    *(float4*)&uu[0] = *(const float4*)&updT[j*TK];
    *(float4*)&uu[4] = *(const float4*)&updT[j*TK+4];
    #pragma unroll
    for (int i=0;i<TK;i++){
      accK[i] = fmaf(wk, uu[i], accK[i]);
      accV[i] = fmaf(wv, uu[i], accV[i]);
    }
  }
  #pragma unroll
  for (int i=0;i<TK;i++){ pk[jg][i][dl]=accK[i]; pv[jg][i][dl]=accV[i]; }
  pq[jg][dl] = accQ;
  __syncthreads();
  int i = tid>>5, dl2 = tid&31;
  float sk=0.f, svv=0.f;
  #pragma unroll
  for (int g2=0; g2<8; g2++){ sk += pk[g2][i][dl2]; svv += pv[g2][i][dl2]; }
  int dd = dc*32+dl2;
  size_t off = ((size_t)(b*MM + idxs[i]))*DD + dd;
  g_K[off] = sk + bk[dd];
  g_V[off] = svv + bv[dd];
  if (i==0 && hasq){
    float sq=0.f;
    #pragma unroll
    for (int g2=0; g2<8; g2++) sq += pq[g2][dl2];
    g_q[b*DD+dd] = sq + bq[dd];
  }
}

// ---------------- launch ----------------

extern "C" void kernel_launch(void* const* d_in, const int* in_sizes, int n_in,
                              void* d_out, int out_size){
  const float* x      = (const float*)d_in[0];
  const float* memory = (const float*)d_in[1];
  const float* Wq     = (const float*)d_in[2];
  const float* bq     = (const float*)d_in[3];
  const float* Wk     = (const float*)d_in[4];
  const float* bk     = (const float*)d_in[5];
  const float* Wv     = (const float*)d_in[6];
  const float* bv     = (const float*)d_in[7];
  const float* Wu     = (const float*)d_in[8];
  const float* bu     = (const float*)d_in[9];
  float* out = (float*)d_out;

  k_transpose<<<256,256>>>(Wq,Wk,Wv,Wu);
  k_init_kv<<<MM/16,256>>>(memory, bk, bv);
  k_init_q<<<BB,256>>>(x, bq);

  for (int t=0; t<SS; t++){
    k_scores<<<dim3(32,BB),256>>>();
    k_memout<<<dim3(16,BB),256>>>();
    k_f1<<<BB,256>>>(out, t);
    k_f2<<<dim3(4,BB),256>>>(x, bu, t);
    k_f3<<<dim3(8,BB),256>>>(x, bq, bk, bv, t);
  }
}